// round 6
// baseline (speedup 1.0000x reference)
#include <cuda_runtime.h>
#include <cstdint>

// RLFrameSelector R6: back to f32x2-FFMA GEMM (R3 skeleton). Changes:
//  - acc pairs over FRAMES (natural from transposed x smem; W duplicated
//    via 4 packs/f-step) -> 3 LDS wf per 16 FMA2 (was 4).
//  - W tile staged with cp.async (contiguous, no transpose) -> no W LDG/STS
//    through the register file / L1 store path.
//  - shfl-based epilogue reduction; topk at 512 threads.

#define BB 32
#define TT 2048
#define FF 512
#define UU 128
#define TM 64        // frames per block
#define FC 16        // f-chunk
#define XST 68       // x smem row stride (floats), 16B-aligned rows

__device__ float         g_scores[BB * TT];
__device__ unsigned char g_sel[BB * TT];

__device__ __forceinline__ unsigned long long fma2(unsigned long long a,
                                                   unsigned long long b,
                                                   unsigned long long c) {
    unsigned long long d;
    asm("fma.rn.f32x2 %0, %1, %2, %3;" : "=l"(d) : "l"(a), "l"(b), "l"(c));
    return d;
}
__device__ __forceinline__ unsigned long long pack2(float v) {
    unsigned long long d;
    asm("mov.b64 %0, {%1, %1};" : "=l"(d) : "f"(v));
    return d;
}
__device__ __forceinline__ float2 unpack2(unsigned long long v) {
    float2 r;
    asm("mov.b64 {%0, %1}, %2;" : "=f"(r.x), "=f"(r.y) : "l"(v));
    return r;
}
__device__ __forceinline__ uint32_t smem_u32(const void* p) {
    uint32_t a;
    asm("{ .reg .u64 t; cvta.to.shared.u64 t, %1; cvt.u32.u64 %0, t; }"
        : "=r"(a) : "l"(p));
    return a;
}
#define CP_ASYNC16(dst, src) \
    asm volatile("cp.async.ca.shared.global [%0], [%1], 16;" \
                 :: "r"(dst), "l"(src) : "memory")
#define CP_COMMIT() asm volatile("cp.async.commit_group;" ::: "memory")
#define CP_WAIT0()  asm volatile("cp.async.wait_group 0;" ::: "memory")

// ---------------------------------------------------------------------------
// Kernel 1: scores. Block = 256 threads.
//   tx = tid&7   -> frames 8*tx .. 8*tx+7 (4 f32x2 frame-pairs)
//   ty = tid>>3  -> units 4*ty .. 4*ty+3
// Per f-step: 2 LDS.128 x (1 wf each, conflict-free) + 1 LDS.128 W (1 wf)
//             + 4 packs + 16 fma.rn.f32x2.
// ---------------------------------------------------------------------------
__global__ __launch_bounds__(256, 3) void score_kernel(
    const float* __restrict__ x,  const float* __restrict__ W1,
    const float* __restrict__ b1, const float* __restrict__ W2,
    const float* __restrict__ b2)
{
    __shared__ float xs[2][FC * XST];      // [buf][f][frame] transposed x
    __shared__ float ws[2][FC * UU];       // [buf][f][u], cp.async target
    __shared__ float red[8 * TM];          // per-warp partial scores
    __shared__ int   nzflag[TM];

    const int tid  = threadIdx.x;
    const int lane = tid & 31;
    const int wid  = tid >> 5;
    const int tx   = tid & 7;
    const int ty   = tid >> 3;
    const int frame0 = blockIdx.x * TM;

    // x loader mapping: one frame per 4 threads
    const int lrow = tid >> 2;             // 0..63
    const int lg   = tid & 3;

    if (tid < TM) nzflag[tid] = 0;

    unsigned long long acc[4][4];          // [frame-pair][unit]
#pragma unroll
    for (int fp = 0; fp < 4; ++fp)
#pragma unroll
        for (int u = 0; u < 4; ++u) acc[fp][u] = 0ull;

    int nz = 0;
    const float* xrow = x + (size_t)(frame0 + lrow) * FF + 4 * lg;

    const uint32_t ws0_a = smem_u32(&ws[0][0]) + tid * 16;
    const uint32_t ws0_b = ws0_a + 4096;
    const uint32_t ws1_a = smem_u32(&ws[1][0]) + tid * 16;
    const uint32_t ws1_b = ws1_a + 4096;

    // ---- prologue: chunk 0
    CP_ASYNC16(ws0_a, W1 + tid * 4);
    CP_ASYNC16(ws0_b, W1 + 1024 + tid * 4);
    CP_COMMIT();
    float4 xv = *(const float4*)(xrow);
    nz |= (xv.x != 0.0f) | (xv.y != 0.0f) | (xv.z != 0.0f) | (xv.w != 0.0f);
    xs[0][(4 * lg + 0) * XST + lrow] = xv.x;
    xs[0][(4 * lg + 1) * XST + lrow] = xv.y;
    xs[0][(4 * lg + 2) * XST + lrow] = xv.z;
    xs[0][(4 * lg + 3) * XST + lrow] = xv.w;
    CP_WAIT0();
    __syncthreads();

#pragma unroll 1
    for (int chunk = 0; chunk < FF / FC; ++chunk) {
        const int  buf  = chunk & 1;
        const bool more = (chunk < FF / FC - 1);

        if (more) {
            xv = *(const float4*)(xrow + (chunk + 1) * FC);
            const float* wsrc = W1 + (chunk + 1) * FC * UU;
            if (buf) { CP_ASYNC16(ws0_a, wsrc + tid * 4);
                       CP_ASYNC16(ws0_b, wsrc + 1024 + tid * 4); }
            else     { CP_ASYNC16(ws1_a, wsrc + tid * 4);
                       CP_ASYNC16(ws1_b, wsrc + 1024 + tid * 4); }
            CP_COMMIT();
        }

        const float* xb = xs[buf];
        const float* wb = ws[buf];

#pragma unroll
        for (int f = 0; f < FC; ++f) {
            // x: frames 8tx..8tx+7 as 4 natural f32x2 pairs
            const ulonglong2 xa = *(const ulonglong2*)(xb + f * XST + 8 * tx);
            const ulonglong2 xc = *(const ulonglong2*)(xb + f * XST + 8 * tx + 4);
            // W: units 4ty..4ty+3
            const float4 wv = *(const float4*)(wb + f * UU + 4 * ty);
            const unsigned long long w0 = pack2(wv.x);
            const unsigned long long w1 = pack2(wv.y);
            const unsigned long long w2 = pack2(wv.z);
            const unsigned long long w3 = pack2(wv.w);

            acc[0][0] = fma2(xa.x, w0, acc[0][0]);
            acc[0][1] = fma2(xa.x, w1, acc[0][1]);
            acc[0][2] = fma2(xa.x, w2, acc[0][2]);
            acc[0][3] = fma2(xa.x, w3, acc[0][3]);
            acc[1][0] = fma2(xa.y, w0, acc[1][0]);
            acc[1][1] = fma2(xa.y, w1, acc[1][1]);
            acc[1][2] = fma2(xa.y, w2, acc[1][2]);
            acc[1][3] = fma2(xa.y, w3, acc[1][3]);
            acc[2][0] = fma2(xc.x, w0, acc[2][0]);
            acc[2][1] = fma2(xc.x, w1, acc[2][1]);
            acc[2][2] = fma2(xc.x, w2, acc[2][2]);
            acc[2][3] = fma2(xc.x, w3, acc[2][3]);
            acc[3][0] = fma2(xc.y, w0, acc[3][0]);
            acc[3][1] = fma2(xc.y, w1, acc[3][1]);
            acc[3][2] = fma2(xc.y, w2, acc[3][2]);
            acc[3][3] = fma2(xc.y, w3, acc[3][3]);
        }

        if (more) {
            nz |= (xv.x != 0.0f) | (xv.y != 0.0f) |
                  (xv.z != 0.0f) | (xv.w != 0.0f);
            const int nb = buf ^ 1;
            xs[nb][(4 * lg + 0) * XST + lrow] = xv.x;
            xs[nb][(4 * lg + 1) * XST + lrow] = xv.y;
            xs[nb][(4 * lg + 2) * XST + lrow] = xv.z;
            xs[nb][(4 * lg + 3) * XST + lrow] = xv.w;
        }
        CP_WAIT0();
        __syncthreads();
    }

    if (nz) nzflag[lrow] = 1;

    // ---- epilogue: relu + W2 dot over this thread's 4 units, 8 frames
    float p[8];
#pragma unroll
    for (int j = 0; j < 8; ++j) p[j] = 0.0f;
#pragma unroll
    for (int u = 0; u < 4; ++u) {
        const int uu = 4 * ty + u;
        const float bv = __ldg(b1 + uu);
        const float wv = __ldg(W2 + uu);
#pragma unroll
        for (int fp = 0; fp < 4; ++fp) {
            const float2 h = unpack2(acc[fp][u]);
            p[2 * fp + 0] += fmaxf(h.x + bv, 0.0f) * wv;
            p[2 * fp + 1] += fmaxf(h.y + bv, 0.0f) * wv;
        }
    }
    // reduce over the 4 ty-groups within the warp (lanes differing in bits 3,4)
#pragma unroll
    for (int j = 0; j < 8; ++j) {
        p[j] += __shfl_xor_sync(0xFFFFFFFFu, p[j], 8);
        p[j] += __shfl_xor_sync(0xFFFFFFFFu, p[j], 16);
    }
    if (lane < 8) {
        *(float4*)&red[wid * TM + 8 * lane]     = make_float4(p[0], p[1], p[2], p[3]);
        *(float4*)&red[wid * TM + 8 * lane + 4] = make_float4(p[4], p[5], p[6], p[7]);
    }
    __syncthreads();

    if (tid < TM) {
        float s = 0.0f;
#pragma unroll
        for (int w = 0; w < 8; ++w) s += red[w * TM + tid];
        s += __ldg(b2);
        g_scores[frame0 + tid] = nzflag[tid] ? s : -1.0e9f;
    }
}

// ---------------------------------------------------------------------------
// Kernel 2: per-batch top-k via 4x8-bit radix select (stable tie-break).
// ---------------------------------------------------------------------------
#define TKT 512
__global__ __launch_bounds__(TKT) void topk_kernel(const int* kptr)
{
    __shared__ unsigned keys[TT];
    __shared__ int      hist[256];
    __shared__ unsigned s_prefix;
    __shared__ int      s_remaining;

    const int b   = blockIdx.x;
    const int tid = threadIdx.x;

    int k = 64;
    if (kptr) {
        int kv = *kptr;
        if (kv > 0 && kv <= TT) k = kv;
        else {
            float kf = __int_as_float(kv);
            if (kf >= 1.0f && kf <= (float)TT) k = (int)kf;
        }
    }

    for (int i = tid; i < TT; i += TKT) {
        unsigned u = __float_as_uint(g_scores[b * TT + i]);
        keys[i] = (u & 0x80000000u) ? ~u : (u | 0x80000000u);
    }
    if (tid == 0) { s_prefix = 0u; s_remaining = k; }
    __syncthreads();

    for (int pass = 3; pass >= 0; --pass) {
        if (tid < 256) hist[tid] = 0;
        __syncthreads();
        const unsigned mhi  = (pass == 3) ? 0u : (0xFFFFFFFFu << ((pass + 1) * 8));
        const unsigned pref = s_prefix;
        const int shift = pass * 8;
        for (int i = tid; i < TT; i += TKT) {
            const unsigned ky = keys[i];
            if ((ky & mhi) == pref) atomicAdd(&hist[(ky >> shift) & 255], 1);
        }
        __syncthreads();
        if (tid == 0) {
            int rem = s_remaining, cum = 0, bin;
            for (bin = 255; bin >= 0; --bin) {
                const int c = hist[bin];
                if (cum + c >= rem) break;
                cum += c;
            }
            s_prefix    = pref | ((unsigned)bin << shift);
            s_remaining = rem - cum;
        }
        __syncthreads();
    }

    const unsigned thr = s_prefix;
    const int need = s_remaining;
    for (int i = tid; i < TT; i += TKT) {
        const unsigned ky = keys[i];
        unsigned char sv = 0;
        if (ky > thr) sv = 1;
        else if (ky == thr) {
            int r = 0;
            for (int j = 0; j < i; ++j) r += (keys[j] == thr);
            sv = (r < need) ? 1 : 0;
        }
        g_sel[b * TT + i] = sv;
    }
}

// ---------------------------------------------------------------------------
// Kernel 3: out = sel ? x : 0.
// ---------------------------------------------------------------------------
__global__ __launch_bounds__(256) void gather_kernel(
    const float* __restrict__ x, float* __restrict__ out)
{
    const int i = blockIdx.x * 256 + threadIdx.x;   // float4 index
    const int frame = i >> 7;                       // 128 float4 per frame
    float4 v = make_float4(0.f, 0.f, 0.f, 0.f);
    if (g_sel[frame]) v = ((const float4*)x)[i];
    ((float4*)out)[i] = v;
}

// ---------------------------------------------------------------------------
extern "C" void kernel_launch(void* const* d_in, const int* in_sizes, int n_in,
                              void* d_out, int out_size)
{
    const float* x  = (const float*)d_in[0];
    const float* W1 = (const float*)d_in[1];
    const float* b1 = (const float*)d_in[2];
    const float* W2 = (const float*)d_in[3];
    const float* b2 = (const float*)d_in[4];
    const int*   kp = (n_in > 5) ? (const int*)d_in[5] : nullptr;

    score_kernel<<<(BB * TT) / TM, 256>>>(x, W1, b1, W2, b2);
    topk_kernel<<<BB, TKT>>>(kp);
    gather_kernel<<<(BB * TT * FF / 4) / 256, 256>>>(x, (float*)d_out);
}